// round 5
// baseline (speedup 1.0000x reference)
#include <cuda_runtime.h>
#include <cstdint>
#include <cstddef>

// Problem constants
#define M_TOK 65536
#define C_DIM 512
#define NQKV  1536
#define HEADS 8
#define HD    64
#define WIN   64
#define NWIN  1024

typedef unsigned long long ull;

// ---------------- scratch ----------------
__device__ float g_xr[(size_t)M_TOK * C_DIM];       // tf32-rounded, k-permuted x
__device__ float g_qkv[(size_t)M_TOK * NQKV];       // qkv projection output
__device__ float g_attnout[(size_t)M_TOK * C_DIM];  // attention out (rounded+permuted)
__device__ float g_wqkvT[(size_t)NQKV * C_DIM];     // Wqkv^T, rounded+permuted
__device__ float g_wprojT[(size_t)C_DIM * C_DIM];   // Wproj^T, rounded+permuted

// ---------------- helpers ----------------
__device__ __forceinline__ float tf32r(float x) {
    uint32_t y; asm("cvt.rna.tf32.f32 %0, %1;" : "=r"(y) : "f"(x));
    return __uint_as_float(y);
}
__device__ __forceinline__ ull pack2(float lo, float hi) {
    ull r; asm("mov.b64 %0, {%1,%2};" : "=l"(r) : "f"(lo), "f"(hi)); return r;
}
__device__ __forceinline__ void unpack2(ull v, float& lo, float& hi) {
    asm("mov.b64 {%0,%1}, %2;" : "=f"(lo), "=f"(hi) : "l"(v));
}
__device__ __forceinline__ void fma2(ull& c, ull a, ull b) {
    asm("fma.rn.f32x2 %0, %1, %2, %0;" : "+l"(c) : "l"(a), "l"(b));
}
__device__ __forceinline__ uint32_t smem_u32(const void* p) {
    uint32_t a;
    asm("{ .reg .u64 t; cvta.to.shared.u64 t, %1; cvt.u32.u64 %0, t; }" : "=r"(a) : "l"(p));
    return a;
}
__device__ __forceinline__ void cpasync16(uint32_t saddr, const void* g) {
    asm volatile("cp.async.cg.shared.global [%0], [%1], 16;" :: "r"(saddr), "l"(g));
}
template<int N> __device__ __forceinline__ void cpwait() {
    asm volatile("cp.async.wait_group %0;" :: "n"(N));
}
__device__ __forceinline__ void cpcommit() {
    asm volatile("cp.async.commit_group;" ::: "memory");
}
__device__ __forceinline__ void lds64(uint32_t& x, uint32_t& y, uint32_t addr) {
    asm volatile("ld.shared.v2.b32 {%0,%1}, [%2];" : "=r"(x), "=r"(y) : "r"(addr));
}
__device__ __forceinline__ void mma_tf32(float* c, const uint32_t* a, const uint32_t* b) {
    asm volatile(
        "mma.sync.aligned.m16n8k8.row.col.f32.tf32.tf32.f32 "
        "{%0,%1,%2,%3}, {%4,%5,%6,%7}, {%8,%9}, {%0,%1,%2,%3};"
        : "+f"(c[0]), "+f"(c[1]), "+f"(c[2]), "+f"(c[3])
        : "r"(a[0]), "r"(a[1]), "r"(a[2]), "r"(a[3]), "r"(b[0]), "r"(b[1]));
}
// permutation within 8-group: k -> [0,4,1,5,2,6,3,7] positions
__device__ __forceinline__ int pi8(int c) {
    return (c & ~7) | ((c & 3) << 1) | ((c >> 2) & 1);
}

// ================= tf32 mma.sync GEMM: C[M,N] = A[M,512] @ BT[N,512]^T =================
// CTA tile 128x256, BK=32, 3-stage cp.async ring, 512 threads, warp tile 32x64.
// Single __syncthreads per k-block; refill issued before compute.
#define BM 128
#define BN 256
#define GBK 32
#define KTOT 512
#define NSTG 3
#define A_ST 16384                   // BM*GBK*4
#define B_ST 32768                   // BN*GBK*4
#define STG_BYTES (A_ST + B_ST)      // 49152
#define GEMM_SMEM (NSTG * STG_BYTES) // 147456

template<bool BIAS>
__global__ __launch_bounds__(512, 1)
void gemm_mma_kernel(const float* __restrict__ A, const float* __restrict__ BT,
                     const float* __restrict__ bias, float* __restrict__ C, int N)
{
    extern __shared__ __align__(128) char smem[];
    const uint32_t sbase = smem_u32(smem);
    const int tid  = threadIdx.x;
    const int warp = tid >> 5;
    const int lane = tid & 31;
    const int g = lane >> 2;      // groupID (0..7)
    const int t = lane & 3;       // thread-in-group
    const int wm = warp & 3;      // 0..3  (m: 4 x 32 = 128)
    const int wn = warp >> 2;     // 0..3  (n: 4 x 64 = 256)
    const int bm = blockIdx.y * BM;
    const int bn = blockIdx.x * BN;

    const int S = KTOT / GBK;     // 16 k-blocks

    auto load_stage = [&](int s) {
        const int slot = s % NSTG;
        const uint32_t sa = sbase + slot * STG_BYTES;
        const uint32_t sb = sa + A_ST;
        const int k0 = s * GBK;
        // A: 128 rows x 8 chunks(16B); plane layout [kk][row][8 floats]
#pragma unroll
        for (int it = 0; it < 2; it++) {
            int i = tid + it * 512;
            int row = i >> 3, ch = i & 7;
            cpasync16(sa + (uint32_t)((ch >> 1) * (BM * 32) + row * 32 + (ch & 1) * 16),
                      A + (size_t)(bm + row) * KTOT + k0 + ch * 4);
        }
        // B: 256 rows x 8 chunks
#pragma unroll
        for (int it = 0; it < 4; it++) {
            int i = tid + it * 512;
            int row = i >> 3, ch = i & 7;
            cpasync16(sb + (uint32_t)((ch >> 1) * (BN * 32) + row * 32 + (ch & 1) * 16),
                      BT + (size_t)(bn + row) * KTOT + k0 + ch * 4);
        }
        cpcommit();
    };

    float c[2][8][4];
#pragma unroll
    for (int i = 0; i < 2; i++)
#pragma unroll
        for (int j = 0; j < 8; j++)
#pragma unroll
            for (int r = 0; r < 4; r++) c[i][j][r] = 0.f;

    // prologue: two stages in flight
    load_stage(0);
    load_stage(1);

    for (int s = 0; s < S; s++) {
        if (s < S - 1) cpwait<1>();
        else cpwait<0>();
        __syncthreads();   // stage s data visible; all warps done computing stage s-1

        if (s + 2 < S) load_stage(s + 2);   // lands in slot (s-1)%3, just freed

        const uint32_t sa = sbase + (s % NSTG) * STG_BYTES;
        const uint32_t sb = sa + A_ST;

#pragma unroll
        for (int kk = 0; kk < 4; kk++) {
            uint32_t a[2][4];
#pragma unroll
            for (int i = 0; i < 2; i++) {
                uint32_t base = sa + (uint32_t)(kk * (BM * 32) + (wm * 32 + i * 16 + g) * 32 + t * 8);
                lds64(a[i][0], a[i][2], base);         // row g
                lds64(a[i][1], a[i][3], base + 256);   // row g+8
            }
            uint32_t b[8][2];
#pragma unroll
            for (int j = 0; j < 8; j++) {
                uint32_t base = sb + (uint32_t)(kk * (BN * 32) + (wn * 64 + j * 8 + g) * 32 + t * 8);
                lds64(b[j][0], b[j][1], base);
            }
#pragma unroll
            for (int i = 0; i < 2; i++)
#pragma unroll
                for (int j = 0; j < 8; j++)
                    mma_tf32(c[i][j], a[i], b[j]);
        }
    }

    // epilogue
#pragma unroll
    for (int i = 0; i < 2; i++) {
        const int row0 = bm + wm * 32 + i * 16 + g;
#pragma unroll
        for (int j = 0; j < 8; j++) {
            const int col = bn + wn * 64 + j * 8 + 2 * t;
            float2 v0 = make_float2(c[i][j][0], c[i][j][1]);
            float2 v1 = make_float2(c[i][j][2], c[i][j][3]);
            if (BIAS) {
                float b0 = bias[col], b1 = bias[col + 1];
                v0.x += b0; v0.y += b1; v1.x += b0; v1.y += b1;
            }
            *(float2*)(C + (size_t)row0 * N + col) = v0;
            *(float2*)(C + (size_t)(row0 + 8) * N + col) = v1;
        }
    }
}

// ================= prep kernels =================
__global__ void round_perm_kernel(const float* __restrict__ in, float* __restrict__ out, int n8)
{
    int i = blockIdx.x * blockDim.x + threadIdx.x;
    int stride = gridDim.x * blockDim.x;
    for (; i < n8; i += stride) {
        float4 a = ((const float4*)in)[2 * i];
        float4 b = ((const float4*)in)[2 * i + 1];
        float4 o0 = make_float4(tf32r(a.x), tf32r(b.x), tf32r(a.y), tf32r(b.y));
        float4 o1 = make_float4(tf32r(a.z), tf32r(b.z), tf32r(a.w), tf32r(b.w));
        ((float4*)out)[2 * i] = o0;
        ((float4*)out)[2 * i + 1] = o1;
    }
}

__global__ void transpose_tf32_kernel(const float* __restrict__ in, float* __restrict__ out,
                                      int R, int Cc)
{
    __shared__ float tile[32][33];
    int c0 = blockIdx.x * 32, r0 = blockIdx.y * 32;
    int tx = threadIdx.x, ty = threadIdx.y;
#pragma unroll
    for (int i = 0; i < 4; i++) {
        int r = r0 + ty + i * 8;
        tile[ty + i * 8][tx] = tf32r(in[(size_t)r * Cc + c0 + tx]);
    }
    __syncthreads();
#pragma unroll
    for (int i = 0; i < 4; i++) {
        int c = c0 + ty + i * 8;
        out[(size_t)c * R + r0 + pi8(tx)] = tile[tx][ty + i * 8];
    }
}

// ================= fused windowed attention (double softmax), fp32 =================
__global__ __launch_bounds__(64) void attn_kernel(
    const float* __restrict__ qkv, float* __restrict__ attnout)
{
    __shared__ float ks[64][64];
    __shared__ float vs[64][64];

    const int w = blockIdx.x, h = blockIdx.y, t = threadIdx.x;
    const float* base = qkv + (size_t)w * WIN * NQKV;

#pragma unroll
    for (int it = 0; it < 16; it++) {
        int f = t + 64 * it;
        int row = f >> 4;
        int c4 = (f & 15) << 2;
        *(float4*)&ks[row][c4] = *(const float4*)(base + (size_t)row * NQKV + 512 + h * HD + c4);
        *(float4*)&vs[row][c4] = *(const float4*)(base + (size_t)row * NQKV + 1024 + h * HD + c4);
    }

    ull q2[32];
    {
        const float* qrow = base + (size_t)t * NQKV + h * HD;
#pragma unroll
        for (int i = 0; i < 16; i++) {
            float4 v = *(const float4*)(qrow + 4 * i);
            q2[2 * i] = pack2(v.x, v.y);
            q2[2 * i + 1] = pack2(v.z, v.w);
        }
    }
    __syncthreads();

    float s[64];
#pragma unroll
    for (int j = 0; j < 64; j++) {
        ull acc = 0ULL;
#pragma unroll
        for (int d = 0; d < 32; d++) fma2(acc, q2[d], *(const ull*)&ks[j][2 * d]);
        float lo, hi; unpack2(acc, lo, hi);
        s[j] = (lo + hi) * 0.125f;
    }

    float m = -1e30f;
#pragma unroll
    for (int j = 0; j < 64; j++) if (j <= t) m = fmaxf(m, s[j]);
    float z = 0.f;
#pragma unroll
    for (int j = 0; j < 64; j++) {
        float e = (j <= t) ? __expf(s[j] - m) : 0.f;
        s[j] = e; z += e;
    }
    const float invz = 1.f / z;

    float z2 = 0.f;
#pragma unroll
    for (int j = 0; j < 64; j++) {
        float e2 = __expf(s[j] * invz);
        s[j] = e2; z2 += e2;
    }
    const float invz2 = 1.f / z2;

    ull o2[32];
#pragma unroll
    for (int d = 0; d < 32; d++) o2[d] = 0ULL;
#pragma unroll
    for (int j = 0; j < 64; j++) {
        ull pp = pack2(s[j] * invz2, s[j] * invz2);
#pragma unroll
        for (int d = 0; d < 32; d++) fma2(o2[d], pp, *(const ull*)&vs[j][2 * d]);
    }

    // unpack, tf32-round, k-permute, store (feeds GEMM2's A operand)
    float f[64];
#pragma unroll
    for (int d = 0; d < 32; d++) unpack2(o2[d], f[2 * d], f[2 * d + 1]);

    float* orow = attnout + ((size_t)(w * WIN + t)) * C_DIM + h * HD;
#pragma unroll
    for (int b = 0; b < 8; b++) {
        const float* fb = f + 8 * b;
        float4 w0 = make_float4(tf32r(fb[0]), tf32r(fb[4]), tf32r(fb[1]), tf32r(fb[5]));
        float4 w1 = make_float4(tf32r(fb[2]), tf32r(fb[6]), tf32r(fb[3]), tf32r(fb[7]));
        *(float4*)(orow + 8 * b) = w0;
        *(float4*)(orow + 8 * b + 4) = w1;
    }
}

// ================= launch =================
extern "C" void kernel_launch(void* const* d_in, const int* in_sizes, int n_in,
                              void* d_out, int out_size)
{
    const float* x     = (const float*)d_in[0];
    const float* Wqkv  = (const float*)d_in[1];
    const float* Wproj = (const float*)d_in[2];
    const float* bproj = (const float*)d_in[3];
    float* out = (float*)d_out;

    float *xr, *qkv, *attnout, *wqkvT, *wprojT;
    cudaGetSymbolAddress((void**)&xr, g_xr);
    cudaGetSymbolAddress((void**)&qkv, g_qkv);
    cudaGetSymbolAddress((void**)&attnout, g_attnout);
    cudaGetSymbolAddress((void**)&wqkvT, g_wqkvT);
    cudaGetSymbolAddress((void**)&wprojT, g_wprojT);

    cudaFuncSetAttribute(gemm_mma_kernel<false>, cudaFuncAttributeMaxDynamicSharedMemorySize, GEMM_SMEM);
    cudaFuncSetAttribute(gemm_mma_kernel<true>,  cudaFuncAttributeMaxDynamicSharedMemorySize, GEMM_SMEM);

    // prep: round+permute x, transpose+round+permute weights
    round_perm_kernel<<<2048, 256>>>(x, xr, (M_TOK * C_DIM) / 8);
    transpose_tf32_kernel<<<dim3(NQKV / 32, C_DIM / 32), dim3(32, 8)>>>(Wqkv, wqkvT, C_DIM, NQKV);
    transpose_tf32_kernel<<<dim3(C_DIM / 32, C_DIM / 32), dim3(32, 8)>>>(Wproj, wprojT, C_DIM, C_DIM);

    // 1) QKV projection: [65536,512] @ [512,1536]
    gemm_mma_kernel<false><<<dim3(NQKV / BN, M_TOK / BM), 512, GEMM_SMEM>>>(
        xr, wqkvT, nullptr, qkv, NQKV);

    // 2) windowed attention (double softmax)
    attn_kernel<<<dim3(NWIN, HEADS), 64>>>(qkv, attnout);

    // 3) output projection + bias: [65536,512] @ [512,512]
    gemm_mma_kernel<true><<<dim3(C_DIM / BN, M_TOK / BM), 512, GEMM_SMEM>>>(
        attnout, wprojT, bproj, out, C_DIM);
}

// round 6
// speedup vs baseline: 1.5110x; 1.5110x over previous
#include <cuda_runtime.h>
#include <cuda_fp16.h>
#include <cstdint>
#include <cstddef>

// Problem constants
#define M_TOK 65536
#define C_DIM 512
#define NQKV  1536
#define HEADS 8
#define HD    64
#define WIN   64
#define NWIN  1024

typedef unsigned long long ull;

// ---------------- scratch ----------------
__device__ __half g_xh[(size_t)M_TOK * C_DIM];       // fp16, pair-permuted x
__device__ float  g_qkv[(size_t)M_TOK * NQKV];       // qkv projection output (fp32)
__device__ __half g_attnh[(size_t)M_TOK * C_DIM];    // attention out (fp16, pair-permuted)
__device__ __half g_wqkvT[(size_t)NQKV * C_DIM];     // Wqkv^T fp16 permuted
__device__ __half g_wprojT[(size_t)C_DIM * C_DIM];   // Wproj^T fp16 permuted

// ---------------- helpers ----------------
__device__ __forceinline__ ull pack2(float lo, float hi) {
    ull r; asm("mov.b64 %0, {%1,%2};" : "=l"(r) : "f"(lo), "f"(hi)); return r;
}
__device__ __forceinline__ void unpack2(ull v, float& lo, float& hi) {
    asm("mov.b64 {%0,%1}, %2;" : "=f"(lo), "=f"(hi) : "l"(v));
}
__device__ __forceinline__ void fma2(ull& c, ull a, ull b) {
    asm("fma.rn.f32x2 %0, %1, %2, %0;" : "+l"(c) : "l"(a), "l"(b));
}
__device__ __forceinline__ uint32_t smem_u32(const void* p) {
    uint32_t a;
    asm("{ .reg .u64 t; cvta.to.shared.u64 t, %1; cvt.u32.u64 %0, t; }" : "=r"(a) : "l"(p));
    return a;
}
__device__ __forceinline__ void cpasync16(uint32_t saddr, const void* g) {
    asm volatile("cp.async.cg.shared.global [%0], [%1], 16;" :: "r"(saddr), "l"(g));
}
template<int N> __device__ __forceinline__ void cpwait() {
    asm volatile("cp.async.wait_group %0;" :: "n"(N));
}
__device__ __forceinline__ void cpcommit() {
    asm volatile("cp.async.commit_group;" ::: "memory");
}
__device__ __forceinline__ void lds64(uint32_t& x, uint32_t& y, uint32_t addr) {
    asm volatile("ld.shared.v2.b32 {%0,%1}, [%2];" : "=r"(x), "=r"(y) : "r"(addr));
}
__device__ __forceinline__ void mma_f16(float* c, const uint32_t* a, const uint32_t* b) {
    asm volatile(
        "mma.sync.aligned.m16n8k16.row.col.f32.f16.f16.f32 "
        "{%0,%1,%2,%3}, {%4,%5,%6,%7}, {%8,%9}, {%0,%1,%2,%3};"
        : "+f"(c[0]), "+f"(c[1]), "+f"(c[2]), "+f"(c[3])
        : "r"(a[0]), "r"(a[1]), "r"(a[2]), "r"(a[3]), "r"(b[0]), "r"(b[1]));
}
__device__ __forceinline__ uint32_t h2pack(float lo, float hi) {
    __half2 h = __floats2half2_rn(lo, hi);
    return *reinterpret_cast<uint32_t*>(&h);
}
// fp16 pair-permutation position within a 16-k group:
// stored slot order is pairs [0,4,1,5,2,6,3,7]; element k -> position:
__device__ __forceinline__ int pi16h(int k) {
    int p = (k >> 1) & 7;
    int s = ((p & 3) << 1) | (p >> 2);
    return (k & ~15) | (s << 1) | (k & 1);
}

// ================= fp16 mma.sync GEMM: C[M,N] = A[M,512] @ BT[N,512]^T =================
// A, BT fp16 pair-permuted. CTA 128x256, GBK=64, 4-stage cp.async, 256 threads,
// warp tile 64x64, single __syncthreads per k-block.
#define BM 128
#define BN 256
#define GBK 64
#define KTOT 512
#define NSTG 4
#define A_ST 16384                    // BM * GBK * 2
#define B_ST 32768                    // BN * GBK * 2
#define STG_BYTES (A_ST + B_ST)       // 49152
#define GEMM_SMEM (NSTG * STG_BYTES)  // 196608

template<bool BIAS>
__global__ __launch_bounds__(256, 1)
void gemm_mma_kernel(const __half* __restrict__ A, const __half* __restrict__ BT,
                     const float* __restrict__ bias, float* __restrict__ C, int N)
{
    extern __shared__ __align__(128) char smem[];
    const uint32_t sbase = smem_u32(smem);
    const int tid  = threadIdx.x;
    const int warp = tid >> 5;
    const int lane = tid & 31;
    const int g = lane >> 2;
    const int t = lane & 3;
    const int wm = warp & 1;      // 0..1 (m: 2 x 64 = 128)
    const int wn = warp >> 1;     // 0..3 (n: 4 x 64 = 256)
    const int bm = blockIdx.y * BM;
    const int bn = blockIdx.x * BN;

    const int S = KTOT / GBK;     // 8 k-blocks

    auto load_stage = [&](int s) {
        const int slot = s & (NSTG - 1);
        const uint32_t sa = sbase + slot * STG_BYTES;
        const uint32_t sb = sa + A_ST;
        const int k0 = s * GBK;
        // A: 128 rows x 8 chunks(16B) -> plane [kk][row][32B]
#pragma unroll
        for (int it = 0; it < 4; it++) {
            int i = tid + it * 256;
            int row = i >> 3, ch = i & 7;
            cpasync16(sa + (uint32_t)((ch >> 1) * (BM * 32) + row * 32 + (ch & 1) * 16),
                      A + (size_t)(bm + row) * KTOT + k0 + ch * 8);
        }
        // B: 256 rows x 8 chunks
#pragma unroll
        for (int it = 0; it < 8; it++) {
            int i = tid + it * 256;
            int row = i >> 3, ch = i & 7;
            cpasync16(sb + (uint32_t)((ch >> 1) * (BN * 32) + row * 32 + (ch & 1) * 16),
                      BT + (size_t)(bn + row) * KTOT + k0 + ch * 8);
        }
        cpcommit();
    };

    float c[4][8][4];
#pragma unroll
    for (int i = 0; i < 4; i++)
#pragma unroll
        for (int j = 0; j < 8; j++)
#pragma unroll
            for (int r = 0; r < 4; r++) c[i][j][r] = 0.f;

    // prologue: three stages in flight
    load_stage(0); load_stage(1); load_stage(2);

    for (int s = 0; s < S; s++) {
        if (s < S - 2) cpwait<2>();
        else if (s == S - 2) cpwait<1>();
        else cpwait<0>();
        __syncthreads();

        if (s + 3 < S) load_stage(s + 3);   // slot (s-1)&3, freed last iteration

        const uint32_t sa = sbase + (s & (NSTG - 1)) * STG_BYTES;
        const uint32_t sb = sa + A_ST;

#pragma unroll
        for (int kk = 0; kk < 4; kk++) {
            uint32_t a[4][4];
#pragma unroll
            for (int i = 0; i < 4; i++) {
                uint32_t base = sa + (uint32_t)(kk * (BM * 32) + (wm * 64 + i * 16 + g) * 32 + t * 8);
                lds64(a[i][0], a[i][2], base);         // row g:   a0 (k-lo), a2 (k-hi)
                lds64(a[i][1], a[i][3], base + 256);   // row g+8: a1, a3
            }
            uint32_t b[8][2];
#pragma unroll
            for (int j = 0; j < 8; j++) {
                uint32_t base = sb + (uint32_t)(kk * (BN * 32) + (wn * 64 + j * 8 + g) * 32 + t * 8);
                lds64(b[j][0], b[j][1], base);
            }
#pragma unroll
            for (int i = 0; i < 4; i++)
#pragma unroll
                for (int j = 0; j < 8; j++)
                    mma_f16(c[i][j], a[i], b[j]);
        }
    }

    // epilogue
#pragma unroll
    for (int i = 0; i < 4; i++) {
        const int row0 = bm + wm * 64 + i * 16 + g;
#pragma unroll
        for (int j = 0; j < 8; j++) {
            const int col = bn + wn * 64 + j * 8 + 2 * t;
            float2 v0 = make_float2(c[i][j][0], c[i][j][1]);
            float2 v1 = make_float2(c[i][j][2], c[i][j][3]);
            if (BIAS) {
                float b0 = bias[col], b1 = bias[col + 1];
                v0.x += b0; v0.y += b1; v1.x += b0; v1.y += b1;
            }
            *(float2*)(C + (size_t)row0 * N + col) = v0;
            *(float2*)(C + (size_t)(row0 + 8) * N + col) = v1;
        }
    }
}

// ================= prep kernels =================
// fp16 round + pair-permute: per 16-float group emit 8 uint32 slots [p0,p4,p1,p5,p2,p6,p3,p7]
__global__ void round_perm_h_kernel(const float* __restrict__ in, uint32_t* __restrict__ out,
                                    int ngroups)
{
    int i = blockIdx.x * blockDim.x + threadIdx.x;
    int stride = gridDim.x * blockDim.x;
    for (; i < ngroups; i += stride) {
        const float4* p = (const float4*)(in + (size_t)i * 16);
        float4 f0 = p[0], f1 = p[1], f2 = p[2], f3 = p[3];
        uint32_t o[8];
        o[0] = h2pack(f0.x, f0.y);   // p0
        o[1] = h2pack(f2.x, f2.y);   // p4
        o[2] = h2pack(f0.z, f0.w);   // p1
        o[3] = h2pack(f2.z, f2.w);   // p5
        o[4] = h2pack(f1.x, f1.y);   // p2
        o[5] = h2pack(f3.x, f3.y);   // p6
        o[6] = h2pack(f1.z, f1.w);   // p3
        o[7] = h2pack(f3.z, f3.w);   // p7
        uint4* q = (uint4*)(out + (size_t)i * 8);
        q[0] = make_uint4(o[0], o[1], o[2], o[3]);
        q[1] = make_uint4(o[4], o[5], o[6], o[7]);
    }
}

// transpose W[K][Cc] -> out[Cc][K] fp16, k pair-permuted
__global__ void transpose_h_kernel(const float* __restrict__ in, __half* __restrict__ out,
                                   int R, int Cc)
{
    __shared__ float tile[32][33];
    int c0 = blockIdx.x * 32, r0 = blockIdx.y * 32;
    int tx = threadIdx.x, ty = threadIdx.y;
#pragma unroll
    for (int i = 0; i < 4; i++) {
        int r = r0 + ty + i * 8;
        tile[ty + i * 8][tx] = in[(size_t)r * Cc + c0 + tx];
    }
    __syncthreads();
#pragma unroll
    for (int i = 0; i < 4; i++) {
        int c = c0 + ty + i * 8;
        out[(size_t)c * R + pi16h(r0 + tx)] = __float2half_rn(tile[tx][ty + i * 8]);
    }
}

// ================= fused windowed attention (double softmax), fp32 =================
__global__ __launch_bounds__(64) void attn_kernel(
    const float* __restrict__ qkv, uint32_t* __restrict__ attnh)
{
    __shared__ float ks[64][64];
    __shared__ float vs[64][64];

    const int w = blockIdx.x, h = blockIdx.y, t = threadIdx.x;
    const float* base = qkv + (size_t)w * WIN * NQKV;

#pragma unroll
    for (int it = 0; it < 16; it++) {
        int f = t + 64 * it;
        int row = f >> 4;
        int c4 = (f & 15) << 2;
        *(float4*)&ks[row][c4] = *(const float4*)(base + (size_t)row * NQKV + 512 + h * HD + c4);
        *(float4*)&vs[row][c4] = *(const float4*)(base + (size_t)row * NQKV + 1024 + h * HD + c4);
    }

    ull q2[32];
    {
        const float* qrow = base + (size_t)t * NQKV + h * HD;
#pragma unroll
        for (int i = 0; i < 16; i++) {
            float4 v = *(const float4*)(qrow + 4 * i);
            q2[2 * i] = pack2(v.x, v.y);
            q2[2 * i + 1] = pack2(v.z, v.w);
        }
    }
    __syncthreads();

    float s[64];
#pragma unroll
    for (int j = 0; j < 64; j++) {
        ull acc = 0ULL;
#pragma unroll
        for (int d = 0; d < 32; d++) fma2(acc, q2[d], *(const ull*)&ks[j][2 * d]);
        float lo, hi; unpack2(acc, lo, hi);
        s[j] = (lo + hi) * 0.125f;
    }

    float m = -1e30f;
#pragma unroll
    for (int j = 0; j < 64; j++) if (j <= t) m = fmaxf(m, s[j]);
    float z = 0.f;
#pragma unroll
    for (int j = 0; j < 64; j++) {
        float e = (j <= t) ? __expf(s[j] - m) : 0.f;
        s[j] = e; z += e;
    }
    const float invz = 1.f / z;

    float z2 = 0.f;
#pragma unroll
    for (int j = 0; j < 64; j++) {
        float e2 = __expf(s[j] * invz);
        s[j] = e2; z2 += e2;
    }
    const float invz2 = 1.f / z2;

    ull o2[32];
#pragma unroll
    for (int d = 0; d < 32; d++) o2[d] = 0ULL;
#pragma unroll
    for (int j = 0; j < 64; j++) {
        ull pp = pack2(s[j] * invz2, s[j] * invz2);
#pragma unroll
        for (int d = 0; d < 32; d++) fma2(o2[d], pp, *(const ull*)&vs[j][2 * d]);
    }

    float f[64];
#pragma unroll
    for (int d = 0; d < 32; d++) unpack2(o2[d], f[2 * d], f[2 * d + 1]);

    // fp16 round + pair-permute, 4 groups of 16 per head chunk
    uint32_t* orow = attnh + ((size_t)(w * WIN + t) * C_DIM + h * HD) / 2;
#pragma unroll
    for (int b = 0; b < 4; b++) {
        const float* fb = f + 16 * b;
        uint32_t* ob = orow + 8 * b;
        ob[0] = h2pack(fb[0],  fb[1]);   // p0
        ob[1] = h2pack(fb[8],  fb[9]);   // p4
        ob[2] = h2pack(fb[2],  fb[3]);   // p1
        ob[3] = h2pack(fb[10], fb[11]);  // p5
        ob[4] = h2pack(fb[4],  fb[5]);   // p2
        ob[5] = h2pack(fb[12], fb[13]);  // p6
        ob[6] = h2pack(fb[6],  fb[7]);   // p3
        ob[7] = h2pack(fb[14], fb[15]);  // p7
    }
}

// ================= launch =================
extern "C" void kernel_launch(void* const* d_in, const int* in_sizes, int n_in,
                              void* d_out, int out_size)
{
    const float* x     = (const float*)d_in[0];
    const float* Wqkv  = (const float*)d_in[1];
    const float* Wproj = (const float*)d_in[2];
    const float* bproj = (const float*)d_in[3];
    float* out = (float*)d_out;

    __half *xh, *attnh, *wqkvT, *wprojT;
    float *qkv;
    cudaGetSymbolAddress((void**)&xh, g_xh);
    cudaGetSymbolAddress((void**)&qkv, g_qkv);
    cudaGetSymbolAddress((void**)&attnh, g_attnh);
    cudaGetSymbolAddress((void**)&wqkvT, g_wqkvT);
    cudaGetSymbolAddress((void**)&wprojT, g_wprojT);

    cudaFuncSetAttribute(gemm_mma_kernel<false>, cudaFuncAttributeMaxDynamicSharedMemorySize, GEMM_SMEM);
    cudaFuncSetAttribute(gemm_mma_kernel<true>,  cudaFuncAttributeMaxDynamicSharedMemorySize, GEMM_SMEM);

    // prep
    round_perm_h_kernel<<<2048, 256>>>(x, (uint32_t*)xh, (M_TOK * C_DIM) / 16);
    transpose_h_kernel<<<dim3(NQKV / 32, C_DIM / 32), dim3(32, 8)>>>(Wqkv, wqkvT, C_DIM, NQKV);
    transpose_h_kernel<<<dim3(C_DIM / 32, C_DIM / 32), dim3(32, 8)>>>(Wproj, wprojT, C_DIM, C_DIM);

    // 1) QKV projection
    gemm_mma_kernel<false><<<dim3(NQKV / BN, M_TOK / BM), 256, GEMM_SMEM>>>(
        xh, wqkvT, nullptr, qkv, NQKV);

    // 2) windowed attention (double softmax)
    attn_kernel<<<dim3(NWIN, HEADS), 64>>>(qkv, (uint32_t*)attnh);

    // 3) output projection + bias
    gemm_mma_kernel<true><<<dim3(C_DIM / BN, M_TOK / BM), 256, GEMM_SMEM>>>(
        attnh, wprojT, bproj, out, C_DIM);
}

// round 7
// speedup vs baseline: 1.5220x; 1.0073x over previous
#include <cuda_runtime.h>
#include <cuda_fp16.h>
#include <cstdint>
#include <cstddef>

// Problem constants
#define M_TOK 65536
#define C_DIM 512
#define NQKV  1536
#define HEADS 8
#define HD    64
#define WIN   64
#define NWIN  1024

typedef unsigned long long ull;

// ---------------- scratch ----------------
__device__ __half g_xh[(size_t)M_TOK * C_DIM];       // fp16, pair-permuted x
__device__ float  g_qkv[(size_t)M_TOK * NQKV];       // qkv projection output (fp32)
__device__ __half g_attnh[(size_t)M_TOK * C_DIM];    // attention out (fp16, pair-permuted)
__device__ __half g_wqkvT[(size_t)NQKV * C_DIM];     // Wqkv^T fp16 permuted
__device__ __half g_wprojT[(size_t)C_DIM * C_DIM];   // Wproj^T fp16 permuted

// ---------------- helpers ----------------
__device__ __forceinline__ ull pack2(float lo, float hi) {
    ull r; asm("mov.b64 %0, {%1,%2};" : "=l"(r) : "f"(lo), "f"(hi)); return r;
}
__device__ __forceinline__ void unpack2(ull v, float& lo, float& hi) {
    asm("mov.b64 {%0,%1}, %2;" : "=f"(lo), "=f"(hi) : "l"(v));
}
__device__ __forceinline__ void fma2(ull& c, ull a, ull b) {
    asm("fma.rn.f32x2 %0, %1, %2, %0;" : "+l"(c) : "l"(a), "l"(b));
}
__device__ __forceinline__ uint32_t smem_u32(const void* p) {
    uint32_t a;
    asm("{ .reg .u64 t; cvta.to.shared.u64 t, %1; cvt.u32.u64 %0, t; }" : "=r"(a) : "l"(p));
    return a;
}
__device__ __forceinline__ void cpasync16(uint32_t saddr, const void* g) {
    asm volatile("cp.async.cg.shared.global [%0], [%1], 16;" :: "r"(saddr), "l"(g));
}
template<int N> __device__ __forceinline__ void cpwait() {
    asm volatile("cp.async.wait_group %0;" :: "n"(N));
}
__device__ __forceinline__ void cpcommit() {
    asm volatile("cp.async.commit_group;" ::: "memory");
}
__device__ __forceinline__ void lds64(uint32_t& x, uint32_t& y, uint32_t addr) {
    asm volatile("ld.shared.v2.b32 {%0,%1}, [%2];" : "=r"(x), "=r"(y) : "r"(addr));
}
__device__ __forceinline__ void mma_f16(float* c, const uint32_t* a, const uint32_t* b) {
    asm volatile(
        "mma.sync.aligned.m16n8k16.row.col.f32.f16.f16.f32 "
        "{%0,%1,%2,%3}, {%4,%5,%6,%7}, {%8,%9}, {%0,%1,%2,%3};"
        : "+f"(c[0]), "+f"(c[1]), "+f"(c[2]), "+f"(c[3])
        : "r"(a[0]), "r"(a[1]), "r"(a[2]), "r"(a[3]), "r"(b[0]), "r"(b[1]));
}
__device__ __forceinline__ uint32_t h2pack(float lo, float hi) {
    __half2 h = __floats2half2_rn(lo, hi);
    return *reinterpret_cast<uint32_t*>(&h);
}
// fp16 pair-permutation position within a 16-k group
__device__ __forceinline__ int pi16h(int k) {
    int p = (k >> 1) & 7;
    int s = ((p & 3) << 1) | (p >> 2);
    return (k & ~15) | (s << 1) | (k & 1);
}

// ================= fp16 mma.sync GEMM: C[M,N] = A[M,512] @ BT[N,512]^T =================
// CTA 128x128, GBK=64, 3-stage cp.async ring (96KB -> 2 CTAs/SM), 256 threads,
// warp tile 64x32, single __syncthreads per k-block.
#define BM 128
#define BN 128
#define GBK 64
#define KTOT 512
#define NSTG 3
#define A_ST 16384                    // BM * GBK * 2
#define B_ST 16384                    // BN * GBK * 2
#define STG_BYTES (A_ST + B_ST)       // 32768
#define GEMM_SMEM (NSTG * STG_BYTES)  // 98304

template<bool BIAS>
__global__ __launch_bounds__(256, 2)
void gemm_mma_kernel(const __half* __restrict__ A, const __half* __restrict__ BT,
                     const float* __restrict__ bias, float* __restrict__ C, int N)
{
    extern __shared__ __align__(128) char smem[];
    const uint32_t sbase = smem_u32(smem);
    const int tid  = threadIdx.x;
    const int warp = tid >> 5;
    const int lane = tid & 31;
    const int g = lane >> 2;
    const int t = lane & 3;
    const int wm = warp & 1;      // 0..1 (m: 2 x 64 = 128)
    const int wn = warp >> 1;     // 0..3 (n: 4 x 32 = 128)
    const int bm = blockIdx.y * BM;
    const int bn = blockIdx.x * BN;

    const int S = KTOT / GBK;     // 8 k-blocks

    auto load_stage = [&](int s) {
        const int slot = s % NSTG;
        const uint32_t sa = sbase + slot * STG_BYTES;
        const uint32_t sb = sa + A_ST;
        const int k0 = s * GBK;
        // A: 128 rows x 8 chunks(16B) -> plane [kk][row][32B]
#pragma unroll
        for (int it = 0; it < 4; it++) {
            int i = tid + it * 256;
            int row = i >> 3, ch = i & 7;
            cpasync16(sa + (uint32_t)((ch >> 1) * (BM * 32) + row * 32 + (ch & 1) * 16),
                      A + (size_t)(bm + row) * KTOT + k0 + ch * 8);
        }
        // B: 128 rows x 8 chunks
#pragma unroll
        for (int it = 0; it < 4; it++) {
            int i = tid + it * 256;
            int row = i >> 3, ch = i & 7;
            cpasync16(sb + (uint32_t)((ch >> 1) * (BN * 32) + row * 32 + (ch & 1) * 16),
                      BT + (size_t)(bn + row) * KTOT + k0 + ch * 8);
        }
        cpcommit();
    };

    float c[4][4][4];
#pragma unroll
    for (int i = 0; i < 4; i++)
#pragma unroll
        for (int j = 0; j < 4; j++)
#pragma unroll
            for (int r = 0; r < 4; r++) c[i][j][r] = 0.f;

    // prologue: two stages in flight
    load_stage(0);
    load_stage(1);

    for (int s = 0; s < S; s++) {
        if (s < S - 1) cpwait<1>();
        else cpwait<0>();
        __syncthreads();   // stage s visible; stage s-1 compute finished by all warps

        if (s + 2 < S) load_stage(s + 2);   // slot (s-1)%3, freed

        const uint32_t sa = sbase + (s % NSTG) * STG_BYTES;
        const uint32_t sb = sa + A_ST;

#pragma unroll
        for (int kk = 0; kk < 4; kk++) {
            uint32_t a[4][4];
#pragma unroll
            for (int i = 0; i < 4; i++) {
                uint32_t base = sa + (uint32_t)(kk * (BM * 32) + (wm * 64 + i * 16 + g) * 32 + t * 8);
                lds64(a[i][0], a[i][2], base);         // row g
                lds64(a[i][1], a[i][3], base + 256);   // row g+8
            }
            uint32_t b[4][2];
#pragma unroll
            for (int j = 0; j < 4; j++) {
                uint32_t base = sb + (uint32_t)(kk * (BN * 32) + (wn * 32 + j * 8 + g) * 32 + t * 8);
                lds64(b[j][0], b[j][1], base);
            }
#pragma unroll
            for (int i = 0; i < 4; i++)
#pragma unroll
                for (int j = 0; j < 4; j++)
                    mma_f16(c[i][j], a[i], b[j]);
        }
    }

    // epilogue
#pragma unroll
    for (int i = 0; i < 4; i++) {
        const int row0 = bm + wm * 64 + i * 16 + g;
#pragma unroll
        for (int j = 0; j < 4; j++) {
            const int col = bn + wn * 32 + j * 8 + 2 * t;
            float2 v0 = make_float2(c[i][j][0], c[i][j][1]);
            float2 v1 = make_float2(c[i][j][2], c[i][j][3]);
            if (BIAS) {
                float b0 = bias[col], b1 = bias[col + 1];
                v0.x += b0; v0.y += b1; v1.x += b0; v1.y += b1;
            }
            *(float2*)(C + (size_t)row0 * N + col) = v0;
            *(float2*)(C + (size_t)(row0 + 8) * N + col) = v1;
        }
    }
}

// ================= prep kernels =================
__global__ void round_perm_h_kernel(const float* __restrict__ in, uint32_t* __restrict__ out,
                                    int ngroups)
{
    int i = blockIdx.x * blockDim.x + threadIdx.x;
    int stride = gridDim.x * blockDim.x;
    for (; i < ngroups; i += stride) {
        const float4* p = (const float4*)(in + (size_t)i * 16);
        float4 f0 = p[0], f1 = p[1], f2 = p[2], f3 = p[3];
        uint32_t o[8];
        o[0] = h2pack(f0.x, f0.y);   // p0
        o[1] = h2pack(f2.x, f2.y);   // p4
        o[2] = h2pack(f0.z, f0.w);   // p1
        o[3] = h2pack(f2.z, f2.w);   // p5
        o[4] = h2pack(f1.x, f1.y);   // p2
        o[5] = h2pack(f3.x, f3.y);   // p6
        o[6] = h2pack(f1.z, f1.w);   // p3
        o[7] = h2pack(f3.z, f3.w);   // p7
        uint4* q = (uint4*)(out + (size_t)i * 8);
        q[0] = make_uint4(o[0], o[1], o[2], o[3]);
        q[1] = make_uint4(o[4], o[5], o[6], o[7]);
    }
}

__global__ void transpose_h_kernel(const float* __restrict__ in, __half* __restrict__ out,
                                   int R, int Cc)
{
    __shared__ float tile[32][33];
    int c0 = blockIdx.x * 32, r0 = blockIdx.y * 32;
    int tx = threadIdx.x, ty = threadIdx.y;
#pragma unroll
    for (int i = 0; i < 4; i++) {
        int r = r0 + ty + i * 8;
        tile[ty + i * 8][tx] = in[(size_t)r * Cc + c0 + tx];
    }
    __syncthreads();
#pragma unroll
    for (int i = 0; i < 4; i++) {
        int c = c0 + ty + i * 8;
        out[(size_t)c * R + pi16h(r0 + tx)] = __float2half_rn(tile[tx][ty + i * 8]);
    }
}

// ================= fused windowed attention (double softmax), fp32 =================
__global__ __launch_bounds__(64) void attn_kernel(
    const float* __restrict__ qkv, uint32_t* __restrict__ attnh)
{
    __shared__ float ks[64][64];
    __shared__ float vs[64][64];

    const int w = blockIdx.x, h = blockIdx.y, t = threadIdx.x;
    const float* base = qkv + (size_t)w * WIN * NQKV;

#pragma unroll
    for (int it = 0; it < 16; it++) {
        int f = t + 64 * it;
        int row = f >> 4;
        int c4 = (f & 15) << 2;
        *(float4*)&ks[row][c4] = *(const float4*)(base + (size_t)row * NQKV + 512 + h * HD + c4);
        *(float4*)&vs[row][c4] = *(const float4*)(base + (size_t)row * NQKV + 1024 + h * HD + c4);
    }

    ull q2[32];
    {
        const float* qrow = base + (size_t)t * NQKV + h * HD;
#pragma unroll
        for (int i = 0; i < 16; i++) {
            float4 v = *(const float4*)(qrow + 4 * i);
            q2[2 * i] = pack2(v.x, v.y);
            q2[2 * i + 1] = pack2(v.z, v.w);
        }
    }
    __syncthreads();

    float s[64];
#pragma unroll
    for (int j = 0; j < 64; j++) {
        ull acc = 0ULL;
#pragma unroll
        for (int d = 0; d < 32; d++) fma2(acc, q2[d], *(const ull*)&ks[j][2 * d]);
        float lo, hi; unpack2(acc, lo, hi);
        s[j] = (lo + hi) * 0.125f;
    }

    float m = -1e30f;
#pragma unroll
    for (int j = 0; j < 64; j++) if (j <= t) m = fmaxf(m, s[j]);
    float z = 0.f;
#pragma unroll
    for (int j = 0; j < 64; j++) {
        float e = (j <= t) ? __expf(s[j] - m) : 0.f;
        s[j] = e; z += e;
    }
    const float invz = 1.f / z;

    float z2 = 0.f;
#pragma unroll
    for (int j = 0; j < 64; j++) {
        float e2 = __expf(s[j] * invz);
        s[j] = e2; z2 += e2;
    }
    const float invz2 = 1.f / z2;

    ull o2[32];
#pragma unroll
    for (int d = 0; d < 32; d++) o2[d] = 0ULL;
#pragma unroll
    for (int j = 0; j < 64; j++) {
        ull pp = pack2(s[j] * invz2, s[j] * invz2);
#pragma unroll
        for (int d = 0; d < 32; d++) fma2(o2[d], pp, *(const ull*)&vs[j][2 * d]);
    }

    float f[64];
#pragma unroll
    for (int d = 0; d < 32; d++) unpack2(o2[d], f[2 * d], f[2 * d + 1]);

    // fp16 round + pair-permute, 4 groups of 16 per head chunk
    uint32_t* orow = attnh + ((size_t)(w * WIN + t) * C_DIM + h * HD) / 2;
#pragma unroll
    for (int b = 0; b < 4; b++) {
        const float* fb = f + 16 * b;
        uint32_t* ob = orow + 8 * b;
        ob[0] = h2pack(fb[0],  fb[1]);   // p0
        ob[1] = h2pack(fb[8],  fb[9]);   // p4
        ob[2] = h2pack(fb[2],  fb[3]);   // p1
        ob[3] = h2pack(fb[10], fb[11]);  // p5
        ob[4] = h2pack(fb[4],  fb[5]);   // p2
        ob[5] = h2pack(fb[12], fb[13]);  // p6
        ob[6] = h2pack(fb[6],  fb[7]);   // p3
        ob[7] = h2pack(fb[14], fb[15]);  // p7
    }
}

// ================= launch =================
extern "C" void kernel_launch(void* const* d_in, const int* in_sizes, int n_in,
                              void* d_out, int out_size)
{
    const float* x     = (const float*)d_in[0];
    const float* Wqkv  = (const float*)d_in[1];
    const float* Wproj = (const float*)d_in[2];
    const float* bproj = (const float*)d_in[3];
    float* out = (float*)d_out;

    __half *xh, *attnh, *wqkvT, *wprojT;
    float *qkv;
    cudaGetSymbolAddress((void**)&xh, g_xh);
    cudaGetSymbolAddress((void**)&qkv, g_qkv);
    cudaGetSymbolAddress((void**)&attnh, g_attnh);
    cudaGetSymbolAddress((void**)&wqkvT, g_wqkvT);
    cudaGetSymbolAddress((void**)&wprojT, g_wprojT);

    cudaFuncSetAttribute(gemm_mma_kernel<false>, cudaFuncAttributeMaxDynamicSharedMemorySize, GEMM_SMEM);
    cudaFuncSetAttribute(gemm_mma_kernel<true>,  cudaFuncAttributeMaxDynamicSharedMemorySize, GEMM_SMEM);

    // prep
    round_perm_h_kernel<<<2048, 256>>>(x, (uint32_t*)xh, (M_TOK * C_DIM) / 16);
    transpose_h_kernel<<<dim3(NQKV / 32, C_DIM / 32), dim3(32, 8)>>>(Wqkv, wqkvT, C_DIM, NQKV);
    transpose_h_kernel<<<dim3(C_DIM / 32, C_DIM / 32), dim3(32, 8)>>>(Wproj, wprojT, C_DIM, C_DIM);

    // 1) QKV projection
    gemm_mma_kernel<false><<<dim3(NQKV / BN, M_TOK / BM), 256, GEMM_SMEM>>>(
        xh, wqkvT, nullptr, qkv, NQKV);

    // 2) windowed attention (double softmax)
    attn_kernel<<<dim3(NWIN, HEADS), 64>>>(qkv, (uint32_t*)attnh);

    // 3) output projection + bias
    gemm_mma_kernel<true><<<dim3(C_DIM / BN, M_TOK / BM), 256, GEMM_SMEM>>>(
        attnh, wprojT, bproj, out, C_DIM);
}

// round 8
// speedup vs baseline: 2.2250x; 1.4619x over previous
#include <cuda_runtime.h>
#include <cuda_fp16.h>
#include <cstdint>
#include <cstddef>

// Problem constants
#define M_TOK 65536
#define C_DIM 512
#define NQKV  1536
#define HEADS 8
#define HD    64
#define WIN   64
#define NWIN  1024

typedef unsigned long long ull;

// ---------------- scratch ----------------
__device__ __half g_xh[(size_t)M_TOK * C_DIM];       // fp16, pair-permuted x
__device__ __half g_qkvh[(size_t)M_TOK * NQKV];      // qkv projection output (fp16, natural)
__device__ __half g_attnh[(size_t)M_TOK * C_DIM];    // attention out (fp16, pair-permuted)
__device__ __half g_wqkvT[(size_t)NQKV * C_DIM];     // Wqkv^T fp16 permuted
__device__ __half g_wprojT[(size_t)C_DIM * C_DIM];   // Wproj^T fp16 permuted

// ---------------- helpers ----------------
__device__ __forceinline__ uint32_t smem_u32(const void* p) {
    uint32_t a;
    asm("{ .reg .u64 t; cvta.to.shared.u64 t, %1; cvt.u32.u64 %0, t; }" : "=r"(a) : "l"(p));
    return a;
}
__device__ __forceinline__ void cpasync16(uint32_t saddr, const void* g) {
    asm volatile("cp.async.cg.shared.global [%0], [%1], 16;" :: "r"(saddr), "l"(g));
}
template<int N> __device__ __forceinline__ void cpwait() {
    asm volatile("cp.async.wait_group %0;" :: "n"(N));
}
__device__ __forceinline__ void cpcommit() {
    asm volatile("cp.async.commit_group;" ::: "memory");
}
__device__ __forceinline__ void lds64(uint32_t& x, uint32_t& y, uint32_t addr) {
    asm volatile("ld.shared.v2.b32 {%0,%1}, [%2];" : "=r"(x), "=r"(y) : "r"(addr));
}
__device__ __forceinline__ void mma_f16(float* c, const uint32_t* a, const uint32_t* b) {
    asm volatile(
        "mma.sync.aligned.m16n8k16.row.col.f32.f16.f16.f32 "
        "{%0,%1,%2,%3}, {%4,%5,%6,%7}, {%8,%9}, {%0,%1,%2,%3};"
        : "+f"(c[0]), "+f"(c[1]), "+f"(c[2]), "+f"(c[3])
        : "r"(a[0]), "r"(a[1]), "r"(a[2]), "r"(a[3]), "r"(b[0]), "r"(b[1]));
}
__device__ __forceinline__ uint32_t h2pack(float lo, float hi) {
    __half2 h = __floats2half2_rn(lo, hi);
    return *reinterpret_cast<uint32_t*>(&h);
}
// fp16 pair-permutation position within a 16-k group (pairs stored [0,4,1,5,2,6,3,7])
__device__ __forceinline__ int pi16h(int k) {
    int p = (k >> 1) & 7;
    int s = ((p & 3) << 1) | (p >> 2);
    return (k & ~15) | (s << 1) | (k & 1);
}

// ================= fp16 mma.sync GEMM: C[M,N] = A[M,512] @ BT[N,512]^T =================
// CTA 128x128, GBK=64, 3-stage cp.async (96KB -> 2 CTAs/SM), 256 threads, warp 64x32.
#define BM 128
#define BN 128
#define GBK 64
#define KTOT 512
#define NSTG 3
#define A_ST 16384
#define B_ST 16384
#define STG_BYTES (A_ST + B_ST)
#define GEMM_SMEM (NSTG * STG_BYTES)

template<bool OUT_HALF, bool BIAS>
__global__ __launch_bounds__(256, 2)
void gemm_mma_kernel(const __half* __restrict__ A, const __half* __restrict__ BT,
                     const float* __restrict__ bias, void* __restrict__ Cv, int N)
{
    extern __shared__ __align__(128) char smem[];
    const uint32_t sbase = smem_u32(smem);
    const int tid  = threadIdx.x;
    const int warp = tid >> 5;
    const int lane = tid & 31;
    const int g = lane >> 2;
    const int t = lane & 3;
    const int wm = warp & 1;
    const int wn = warp >> 1;
    const int bm = blockIdx.y * BM;
    const int bn = blockIdx.x * BN;

    const int S = KTOT / GBK;

    auto load_stage = [&](int s) {
        const int slot = s % NSTG;
        const uint32_t sa = sbase + slot * STG_BYTES;
        const uint32_t sb = sa + A_ST;
        const int k0 = s * GBK;
#pragma unroll
        for (int it = 0; it < 4; it++) {
            int i = tid + it * 256;
            int row = i >> 3, ch = i & 7;
            cpasync16(sa + (uint32_t)((ch >> 1) * (BM * 32) + row * 32 + (ch & 1) * 16),
                      A + (size_t)(bm + row) * KTOT + k0 + ch * 8);
        }
#pragma unroll
        for (int it = 0; it < 4; it++) {
            int i = tid + it * 256;
            int row = i >> 3, ch = i & 7;
            cpasync16(sb + (uint32_t)((ch >> 1) * (BN * 32) + row * 32 + (ch & 1) * 16),
                      BT + (size_t)(bn + row) * KTOT + k0 + ch * 8);
        }
        cpcommit();
    };

    float c[4][4][4];
#pragma unroll
    for (int i = 0; i < 4; i++)
#pragma unroll
        for (int j = 0; j < 4; j++)
#pragma unroll
            for (int r = 0; r < 4; r++) c[i][j][r] = 0.f;

    load_stage(0);
    load_stage(1);

    for (int s = 0; s < S; s++) {
        if (s < S - 1) cpwait<1>();
        else cpwait<0>();
        __syncthreads();

        if (s + 2 < S) load_stage(s + 2);

        const uint32_t sa = sbase + (s % NSTG) * STG_BYTES;
        const uint32_t sb = sa + A_ST;

#pragma unroll
        for (int kk = 0; kk < 4; kk++) {
            uint32_t a[4][4];
#pragma unroll
            for (int i = 0; i < 4; i++) {
                uint32_t base = sa + (uint32_t)(kk * (BM * 32) + (wm * 64 + i * 16 + g) * 32 + t * 8);
                lds64(a[i][0], a[i][2], base);
                lds64(a[i][1], a[i][3], base + 256);
            }
            uint32_t b[4][2];
#pragma unroll
            for (int j = 0; j < 4; j++) {
                uint32_t base = sb + (uint32_t)(kk * (BN * 32) + (wn * 32 + j * 8 + g) * 32 + t * 8);
                lds64(b[j][0], b[j][1], base);
            }
#pragma unroll
            for (int i = 0; i < 4; i++)
#pragma unroll
                for (int j = 0; j < 4; j++)
                    mma_f16(c[i][j], a[i], b[j]);
        }
    }

    // epilogue
#pragma unroll
    for (int i = 0; i < 4; i++) {
        const int row0 = bm + wm * 64 + i * 16 + g;
#pragma unroll
        for (int j = 0; j < 4; j++) {
            const int col = bn + wn * 32 + j * 8 + 2 * t;
            if (OUT_HALF) {
                uint32_t* Ch = (uint32_t*)Cv;
                Ch[(size_t)row0 * (N / 2) + (col >> 1)] = h2pack(c[i][j][0], c[i][j][1]);
                Ch[(size_t)(row0 + 8) * (N / 2) + (col >> 1)] = h2pack(c[i][j][2], c[i][j][3]);
            } else {
                float* C = (float*)Cv;
                float2 v0 = make_float2(c[i][j][0], c[i][j][1]);
                float2 v1 = make_float2(c[i][j][2], c[i][j][3]);
                if (BIAS) {
                    float b0 = bias[col], b1 = bias[col + 1];
                    v0.x += b0; v0.y += b1; v1.x += b0; v1.y += b1;
                }
                *(float2*)(C + (size_t)row0 * N + col) = v0;
                *(float2*)(C + (size_t)(row0 + 8) * N + col) = v1;
            }
        }
    }
}

// ================= prep kernels =================
__global__ void round_perm_h_kernel(const float* __restrict__ in, uint32_t* __restrict__ out,
                                    int ngroups)
{
    int i = blockIdx.x * blockDim.x + threadIdx.x;
    int stride = gridDim.x * blockDim.x;
    for (; i < ngroups; i += stride) {
        const float4* p = (const float4*)(in + (size_t)i * 16);
        float4 f0 = p[0], f1 = p[1], f2 = p[2], f3 = p[3];
        uint4 q0, q1;
        q0.x = h2pack(f0.x, f0.y);   // p0
        q0.y = h2pack(f2.x, f2.y);   // p4
        q0.z = h2pack(f0.z, f0.w);   // p1
        q0.w = h2pack(f2.z, f2.w);   // p5
        q1.x = h2pack(f1.x, f1.y);   // p2
        q1.y = h2pack(f3.x, f3.y);   // p6
        q1.z = h2pack(f1.z, f1.w);   // p3
        q1.w = h2pack(f3.z, f3.w);   // p7
        uint4* q = (uint4*)(out + (size_t)i * 8);
        q[0] = q0;
        q[1] = q1;
    }
}

__global__ void transpose_h_kernel(const float* __restrict__ in, __half* __restrict__ out,
                                   int R, int Cc)
{
    __shared__ float tile[32][33];
    int c0 = blockIdx.x * 32, r0 = blockIdx.y * 32;
    int tx = threadIdx.x, ty = threadIdx.y;
#pragma unroll
    for (int i = 0; i < 4; i++) {
        int r = r0 + ty + i * 8;
        tile[ty + i * 8][tx] = in[(size_t)r * Cc + c0 + tx];
    }
    __syncthreads();
#pragma unroll
    for (int i = 0; i < 4; i++) {
        int c = c0 + ty + i * 8;
        out[(size_t)c * R + pi16h(r0 + tx)] = __float2half_rn(tile[tx][ty + i * 8]);
    }
}

// ================= tensor-core windowed attention (double softmax) =================
// One CTA per (window, head). 4 warps; warp m owns query rows [16m, 16m+16).
// S = Q@K^T and O = P@V via m16n8k16; softmax on fragments with shfl over t-group.
__global__ __launch_bounds__(128) void attn_mma_kernel(
    const __half* __restrict__ qkvh, uint32_t* __restrict__ attnh)
{
    __shared__ __half qs[64][72];   // pad to 72 halves: conflict-free fragment loads
    __shared__ __half ks[64][72];
    __shared__ __half vt[64][72];   // V transposed: vt[d][token]

    const int w = blockIdx.x, h = blockIdx.y;
    const int tid = threadIdx.x;
    const int warp = tid >> 5, lane = tid & 31;
    const int g = lane >> 2, t = lane & 3;
    const int mr = warp * 16;

    const size_t base = (size_t)(w * WIN) * NQKV + (size_t)h * HD;

    // load Q, K tiles; V transposed on the fly
#pragma unroll
    for (int it = 0; it < 4; it++) {
        int i = tid + it * 128;
        int j = i >> 3, ch = i & 7;
        *(uint4*)&qs[j][ch * 8] = *(const uint4*)(qkvh + base + (size_t)j * NQKV + ch * 8);
        *(uint4*)&ks[j][ch * 8] = *(const uint4*)(qkvh + base + 512 + (size_t)j * NQKV + ch * 8);
        uint4 vv = *(const uint4*)(qkvh + base + 1024 + (size_t)j * NQKV + ch * 8);
        const __half* vh = (const __half*)&vv;
#pragma unroll
        for (int e = 0; e < 8; e++) vt[ch * 8 + e][j] = vh[e];
    }
    __syncthreads();

    // ---- S = Q @ K^T (scaled) ----
    float sc[8][4];
#pragma unroll
    for (int jn = 0; jn < 8; jn++)
#pragma unroll
        for (int r = 0; r < 4; r++) sc[jn][r] = 0.f;

#pragma unroll
    for (int kb = 0; kb < 4; kb++) {
        uint32_t a[4];
        a[0] = *(const uint32_t*)&qs[mr + g][kb * 16 + 2 * t];
        a[1] = *(const uint32_t*)&qs[mr + g + 8][kb * 16 + 2 * t];
        a[2] = *(const uint32_t*)&qs[mr + g][kb * 16 + 2 * t + 8];
        a[3] = *(const uint32_t*)&qs[mr + g + 8][kb * 16 + 2 * t + 8];
#pragma unroll
        for (int jn = 0; jn < 8; jn++) {
            uint32_t b[2];
            b[0] = *(const uint32_t*)&ks[jn * 8 + g][kb * 16 + 2 * t];
            b[1] = *(const uint32_t*)&ks[jn * 8 + g][kb * 16 + 2 * t + 8];
            mma_f16(sc[jn], a, b);
        }
    }

    // ---- double softmax on fragments ----
    // thread holds rows r0=mr+g (sc[jn][0..1]) and r1=mr+g+8 (sc[jn][2..3]),
    // cols jn*8 + 2t + e. Full row = this thread + 3 shfl partners (t-group).
    const int r0 = mr + g, r1 = mr + g + 8;
    float p0v[16], p1v[16];
    float m0 = -1e30f, m1 = -1e30f;
#pragma unroll
    for (int jn = 0; jn < 8; jn++) {
#pragma unroll
        for (int e = 0; e < 2; e++) {
            int col = jn * 8 + 2 * t + e;
            float v0 = sc[jn][e] * 0.125f;
            float v1 = sc[jn][2 + e] * 0.125f;
            p0v[2 * jn + e] = v0;
            p1v[2 * jn + e] = v1;
            if (col <= r0) m0 = fmaxf(m0, v0);
            if (col <= r1) m1 = fmaxf(m1, v1);
        }
    }
    m0 = fmaxf(m0, __shfl_xor_sync(0xffffffffu, m0, 1));
    m0 = fmaxf(m0, __shfl_xor_sync(0xffffffffu, m0, 2));
    m1 = fmaxf(m1, __shfl_xor_sync(0xffffffffu, m1, 1));
    m1 = fmaxf(m1, __shfl_xor_sync(0xffffffffu, m1, 2));

    float z0 = 0.f, z1 = 0.f;
#pragma unroll
    for (int jn = 0; jn < 8; jn++) {
#pragma unroll
        for (int e = 0; e < 2; e++) {
            int col = jn * 8 + 2 * t + e;
            float e0 = (col <= r0) ? __expf(p0v[2 * jn + e] - m0) : 0.f;
            float e1 = (col <= r1) ? __expf(p1v[2 * jn + e] - m1) : 0.f;
            p0v[2 * jn + e] = e0;
            p1v[2 * jn + e] = e1;
            z0 += e0; z1 += e1;
        }
    }
    z0 += __shfl_xor_sync(0xffffffffu, z0, 1);
    z0 += __shfl_xor_sync(0xffffffffu, z0, 2);
    z1 += __shfl_xor_sync(0xffffffffu, z1, 1);
    z1 += __shfl_xor_sync(0xffffffffu, z1, 2);
    const float iz0 = 1.f / z0, iz1 = 1.f / z1;

    // softmax #2 over the FULL axis (masked entries are exactly 0 -> exp(0)=1)
    float z20 = 0.f, z21 = 0.f;
#pragma unroll
    for (int i = 0; i < 16; i++) {
        float e0 = __expf(p0v[i] * iz0);
        float e1 = __expf(p1v[i] * iz1);
        p0v[i] = e0; p1v[i] = e1;
        z20 += e0; z21 += e1;
    }
    z20 += __shfl_xor_sync(0xffffffffu, z20, 1);
    z20 += __shfl_xor_sync(0xffffffffu, z20, 2);
    z21 += __shfl_xor_sync(0xffffffffu, z21, 1);
    z21 += __shfl_xor_sync(0xffffffffu, z21, 2);
    const float iz20 = 1.f / z20, iz21 = 1.f / z21;

    // ---- O = P @ V ----
    float oc[8][4];
#pragma unroll
    for (int jd = 0; jd < 8; jd++)
#pragma unroll
        for (int r = 0; r < 4; r++) oc[jd][r] = 0.f;

#pragma unroll
    for (int kb = 0; kb < 4; kb++) {
        uint32_t a[4];
        a[0] = h2pack(p0v[4 * kb + 0] * iz20, p0v[4 * kb + 1] * iz20);
        a[1] = h2pack(p1v[4 * kb + 0] * iz21, p1v[4 * kb + 1] * iz21);
        a[2] = h2pack(p0v[4 * kb + 2] * iz20, p0v[4 * kb + 3] * iz20);
        a[3] = h2pack(p1v[4 * kb + 2] * iz21, p1v[4 * kb + 3] * iz21);
#pragma unroll
        for (int jd = 0; jd < 8; jd++) {
            uint32_t b[2];
            b[0] = *(const uint32_t*)&vt[jd * 8 + g][kb * 16 + 2 * t];
            b[1] = *(const uint32_t*)&vt[jd * 8 + g][kb * 16 + 2 * t + 8];
            mma_f16(oc[jd], a, b);
        }
    }

    // ---- epilogue: fp16 pair-permuted store (GEMM2 A-operand layout) ----
    const int tok0 = w * WIN + mr + g;
    uint32_t* orow0 = attnh + (size_t)tok0 * (C_DIM / 2) + h * (HD / 2);
    uint32_t* orow1 = orow0 + 8 * (C_DIM / 2);
#pragma unroll
    for (int jd = 0; jd < 8; jd++) {
        int woff = ((jd >> 1) << 3) + (t << 1) + (jd & 1);
        orow0[woff] = h2pack(oc[jd][0], oc[jd][1]);
        orow1[woff] = h2pack(oc[jd][2], oc[jd][3]);
    }
}

// ================= launch =================
extern "C" void kernel_launch(void* const* d_in, const int* in_sizes, int n_in,
                              void* d_out, int out_size)
{
    const float* x     = (const float*)d_in[0];
    const float* Wqkv  = (const float*)d_in[1];
    const float* Wproj = (const float*)d_in[2];
    const float* bproj = (const float*)d_in[3];
    float* out = (float*)d_out;

    __half *xh, *qkvh, *attnh, *wqkvT, *wprojT;
    cudaGetSymbolAddress((void**)&xh, g_xh);
    cudaGetSymbolAddress((void**)&qkvh, g_qkvh);
    cudaGetSymbolAddress((void**)&attnh, g_attnh);
    cudaGetSymbolAddress((void**)&wqkvT, g_wqkvT);
    cudaGetSymbolAddress((void**)&wprojT, g_wprojT);

    cudaFuncSetAttribute((const void*)gemm_mma_kernel<true, false>,
                         cudaFuncAttributeMaxDynamicSharedMemorySize, GEMM_SMEM);
    cudaFuncSetAttribute((const void*)gemm_mma_kernel<false, true>,
                         cudaFuncAttributeMaxDynamicSharedMemorySize, GEMM_SMEM);

    // prep
    round_perm_h_kernel<<<2048, 256>>>(x, (uint32_t*)xh, (M_TOK * C_DIM) / 16);
    transpose_h_kernel<<<dim3(NQKV / 32, C_DIM / 32), dim3(32, 8)>>>(Wqkv, wqkvT, C_DIM, NQKV);
    transpose_h_kernel<<<dim3(C_DIM / 32, C_DIM / 32), dim3(32, 8)>>>(Wproj, wprojT, C_DIM, C_DIM);

    // 1) QKV projection -> fp16 qkv
    gemm_mma_kernel<true, false><<<dim3(NQKV / BN, M_TOK / BM), 256, GEMM_SMEM>>>(
        xh, wqkvT, nullptr, qkvh, NQKV);

    // 2) windowed attention (double softmax) on tensor cores
    attn_mma_kernel<<<dim3(NWIN, HEADS), 128>>>(qkvh, (uint32_t*)attnh);

    // 3) output projection + bias (fp32 out)
    gemm_mma_kernel<false, true><<<dim3(C_DIM / BN, M_TOK / BM), 256, GEMM_SMEM>>>(
        attnh, wprojT, bproj, out, C_DIM);
}